// round 6
// baseline (speedup 1.0000x reference)
#include <cuda_runtime.h>
#include <math.h>

#define FULLMASK 0xFFFFFFFFu

// ---------------- scratch (no allocations allowed) ----------------
__device__ double g_acc[8];              // 0..2 ifd0..2, 3..4 scr0..1
__device__ double g_main_part[32];
__device__ float  g_part0[32 * 64 * 64];   // [b][k][c]
__device__ float  g_part1[32 * 32 * 128];
__device__ float  g_part2[32 * 16 * 256];
__device__ int    g_sel0[64];
__device__ int    g_sel1[128];
__device__ int    g_cnt[96];             // [b*3 + f]
__device__ int    g_setup_done;
__device__ int    g_done;                // 3584 ifd + 32 main

// ---- dynamic smem layout (floats): tile 16384 | ns 256 | sel 128 | fl 64 | shd 32 | tex 2048
#define OFF_NS   16384
#define OFF_SEL  16640
#define OFF_FL   16768
#define OFF_SHD  16832
#define OFF_TEX  16864
#define SMEM_FLOATS 18912
#define SMEM_BYTES  (SMEM_FLOATS * 4)

// ---------------- threefry2x32-20 (exact JAX semantics) ----------------
__device__ __forceinline__ void tf2x32(unsigned k0, unsigned k1,
                                       unsigned x0, unsigned x1,
                                       unsigned& o0, unsigned& o1) {
  unsigned ks2 = 0x1BD11BDAu ^ k0 ^ k1;
#define TFR(r) { x0 += x1; x1 = (x1 << (r)) | (x1 >> (32 - (r))); x1 ^= x0; }
  x0 += k0; x1 += k1;
  TFR(13) TFR(15) TFR(26) TFR(6)   x0 += k1;  x1 += ks2 + 1u;
  TFR(17) TFR(29) TFR(16) TFR(24)  x0 += ks2; x1 += k0 + 2u;
  TFR(13) TFR(15) TFR(26) TFR(6)   x0 += k0;  x1 += k1 + 3u;
  TFR(17) TFR(29) TFR(16) TFR(24)  x0 += k1;  x1 += ks2 + 4u;
  TFR(13) TFR(15) TFR(26) TFR(6)   x0 += ks2; x1 += k0 + 5u;
#undef TFR
  o0 = x0; o1 = x1;
}

__device__ __forceinline__ void warp_red(float& s) {
  for (int o = 16; o; o >>= 1) s += __shfl_down_sync(FULLMASK, s, o);
}

__device__ void setup_body(float* sm) {
  unsigned* keys = (unsigned*)(sm);          // reuse tile region
  int* perm = (int*)(sm + 256);
  int t = threadIdx.x;
#pragma unroll 1
  for (int i = 0; i < 2; i++) {
    unsigned kf0, kf1;
    tf2x32(0u, 42u, 0u, (unsigned)i, kf0, kf1);
    unsigned a0, a1, b0, b1;
    tf2x32(kf0, kf1, 0u, 2u, a0, a1);
    tf2x32(kf0, kf1, 1u, 3u, b0, b1);
    unsigned kt0 = a1, kt1 = b1;
    unsigned c0, c1, d0, d1;
    tf2x32(kt0, kt1, 0u, 2u, c0, c1);
    tf2x32(kt0, kt1, 1u, 3u, d0, d1);
    unsigned sk0 = c1, sk1 = d1;
    (void)a0; (void)b0; (void)c0; (void)d0;
    if (t < 128) {
      unsigned y0, y1;
      tf2x32(sk0, sk1, (unsigned)t, (unsigned)(t + 128), y0, y1);
      keys[t] = y0; keys[t + 128] = y1;
    }
    __syncthreads();
    unsigned my = keys[t];
    int rank = 0;
    for (int j = 0; j < 256; j++) {
      unsigned kj = keys[j];
      rank += (kj < my) || (kj == my && j < t);
    }
    perm[rank] = t;
    __syncthreads();
    if (i == 0) { if (t <  64) g_sel0[t] = perm[t]; }
    else        { if (t < 128) g_sel1[t] = perm[t]; }
    __syncthreads();
  }
  __threadfence();
  __syncthreads();
  if (t == 0) atomicExch(&g_setup_done, 1);
}

__device__ __forceinline__ void publish(int cidx) {
  __threadfence();
  __syncthreads();
  if (threadIdx.x == 0) atomicAdd(&g_cnt[cidx], 1);
}

__device__ __forceinline__ void wait_cnt(int cidx, int K, bool need_setup) {
  if (threadIdx.x == 0) {
    volatile int* c = &g_cnt[cidx];
    while (*c < K) __nanosleep(32);
    if (need_setup) {
      volatile int* s = &g_setup_done;
      while (*s == 0) __nanosleep(32);
    }
    __threadfence();
  }
  __syncthreads();
}

template <bool HAS_T>
__device__ __forceinline__ void ifd_epilogue(float ifd, float scr, int AI, int AS,
                                             double* shd) {
  double di = (double)ifd, ds = (double)scr;
  for (int o = 16; o; o >>= 1) {
    di += __shfl_down_sync(FULLMASK, di, o);
    if (HAS_T) ds += __shfl_down_sync(FULLMASK, ds, o);
  }
  int t = threadIdx.x, wid = t >> 5;
  if ((t & 31) == 0) { shd[wid] = di; if (HAS_T) shd[8 + wid] = ds; }
  __syncthreads();
  if (t == 0) {
    double ti = 0.0, ts = 0.0;
    for (int i = 0; i < 8; i++) { ti += shd[i]; if (HAS_T) ts += shd[8 + i]; }
    atomicAdd(&g_acc[AI], ti);
    if (HAS_T) atomicAdd(&g_acc[AS], ts);
    __threadfence();
    atomicAdd(&g_done, 1);
  }
}

// rank flags from ns[] into fl[]; strong = top C/2 (stable argsort of -norm)
template <int C>
__device__ __forceinline__ void rank_flags(const float* ns, unsigned char* fl) {
  int t = threadIdx.x;
  if (t < C) {
    float v = ns[t];
    int rank = 0;
#pragma unroll 4
    for (int j = 0; j < C; j++) {
      float nj = ns[j];
      rank += (nj > v) || (nj == v && j < t);
    }
    fl[t] = (rank < C / 2) ? (unsigned char)0 : (unsigned char)1;
  }
  __syncthreads();
}

// ---------------- feat0: C=64, HW=16384, tile 64x256, K=64 blocks/batch ----------------
__device__ void body_f0(float* sm, const float* __restrict__ f0,
                        const float* __restrict__ f2, int b, int pb) {
  float* tile = sm;
  float* ns  = sm + OFF_NS;          // doubles as wsum[c*2+h]
  int*   sel = (int*)(sm + OFF_SEL);
  unsigned char* fl = (unsigned char*)(sm + OFF_FL);
  double* shd = (double*)(sm + OFF_SHD);
  float* tex = sm + OFF_TEX;
  int t = threadIdx.x, w = t >> 5, lane = t & 31;

  const float* base = f0 + (size_t)b * 64 * 16384 + pb * 256;
#pragma unroll
  for (int k = 0; k < 16; k++) {
    int i = k * 256 + t;
    int c = i >> 6, j = i & 63;
    float4 q = *(const float4*)(base + (size_t)c * 16384 + j * 4);
    ((float4*)tile)[c * 64 + j] = q;
    float s = q.x * q.x + q.y * q.y + q.z * q.z + q.w * q.w;
    warp_red(s);
    if (lane == 0) ns[c * 2 + (w & 1)] = s;   // c = k*4 + (w>>1): unique slot
  }
  __syncthreads();
  if (t < 64) g_part0[((b * 64) + pb) * 64 + t] = ns[t * 2] + ns[t * 2 + 1];
  publish(b * 3 + 0);
  wait_cnt(b * 3 + 0, 64, true);

  if (t < 64) {
    float s = 0.f;
    const float* pp = &g_part0[b * 64 * 64 + t];
#pragma unroll 4
    for (int k = 0; k < 64; k++) s += pp[k * 64];
    ns[t] = s;
    sel[t] = g_sel0[t];
  }
  __syncthreads();
  rank_flags<64>(ns, fl);

  // stage teacher tile: 64 sel-channels x 32 texels
  const float* tb = f2 + (size_t)b * 256 * 1024 + (pb >> 1) * 32;
  for (int idx = t; idx < 2048; idx += 256) {
    int c = idx >> 5, j = idx & 31;
    tex[idx] = tb[(size_t)sel[c] * 1024 + j];
  }
  __syncthreads();

  int tcol = (t & 127) >> 2;
  float sS = 0.f, sW = 0.f, scr = 0.f;
#pragma unroll 8
  for (int c = 0; c < 64; c++) {
    float v = tile[c * 256 + t];
    float tv = tex[c * 32 + tcol];
    if (fl[c]) sW += v; else sS += v;
    float d = v - tv;
    scr += d * d;
  }
  float aS = 1.f / (1.f + expf(-sS * (1.f / 32.f)));
  float aW = 1.f / (1.f + expf(-sW * (1.f / 32.f)));
  float dd = aW - aS;
  ifd_epilogue<true>(dd * dd, scr, 0, 3, shd);
}

// ---------------- feat1: C=128, HW=4096, tile 128x128, K=32 blocks/batch ----------------
__device__ void body_f1(float* sm, const float* __restrict__ f1,
                        const float* __restrict__ f2, int b, int pb) {
  float* tile = sm;
  float* ns  = sm + OFF_NS;
  int*   sel = (int*)(sm + OFF_SEL);
  unsigned char* fl = (unsigned char*)(sm + OFF_FL);
  double* shd = (double*)(sm + OFF_SHD);
  float* comb = sm + OFF_TEX;        // combS[128] @0, combW[128] @128
  int t = threadIdx.x, w = t >> 5, lane = t & 31;

  const float* base = f1 + (size_t)b * 128 * 4096 + pb * 128;
#pragma unroll
  for (int k = 0; k < 16; k++) {
    int i = k * 256 + t;
    int c = i >> 5, j = i & 31;      // c = k*8 + w
    float4 q = *(const float4*)(base + (size_t)c * 4096 + j * 4);
    ((float4*)tile)[c * 32 + j] = q;
    float s = q.x * q.x + q.y * q.y + q.z * q.z + q.w * q.w;
    warp_red(s);
    if (lane == 0) ns[c] = s;
  }
  __syncthreads();
  if (t < 128) g_part1[((b * 32) + pb) * 128 + t] = ns[t];
  publish(b * 3 + 1);
  wait_cnt(b * 3 + 1, 32, true);

  if (t < 128) {
    float s = 0.f;
    const float* pp = &g_part1[b * 32 * 128 + t];
#pragma unroll 4
    for (int k = 0; k < 32; k++) s += pp[k * 128];
    ns[t] = s;
    sel[t] = g_sel1[t];
  }
  __syncthreads();
  rank_flags<128>(ns, fl);

  int p = t & 127, g = t >> 7;       // group g handles channels [g*64, g*64+64)
  int tpix = pb * 32 + ((p & 63) >> 1);
  const float* tb = f2 + (size_t)b * 256 * 1024;
  float sS = 0.f, sW = 0.f, scr = 0.f;
#pragma unroll 8
  for (int cc = 0; cc < 64; cc++) {
    int c = g * 64 + cc;
    float v = tile[c * 128 + p];
    float tv = __ldg(tb + (size_t)sel[c] * 1024 + tpix);
    if (fl[c]) sW += v; else sS += v;
    float d = v - tv;
    scr += d * d;
  }
  if (g == 1) { comb[p] = sS; comb[128 + p] = sW; }
  __syncthreads();
  float ifd = 0.f;
  if (g == 0) {
    float tS = sS + comb[p], tW = sW + comb[128 + p];
    float aS = 1.f / (1.f + expf(-tS * (1.f / 64.f)));
    float aW = 1.f / (1.f + expf(-tW * (1.f / 64.f)));
    float dd = aW - aS;
    ifd = dd * dd;
  }
  ifd_epilogue<true>(ifd, scr, 1, 4, shd);
}

// ---------------- feat2: C=256, HW=1024, tile 256x64, K=16 blocks/batch ----------------
__device__ void body_f2(float* sm, const float* __restrict__ f2, int b, int pb) {
  float* tile = sm;
  float* ns  = sm + OFF_NS;
  unsigned char* fl = (unsigned char*)(sm + OFF_FL);
  double* shd = (double*)(sm + OFF_SHD);
  float* comb = sm + OFF_TEX;        // combS[256] @0, combW[256] @256
  int t = threadIdx.x, lane = t & 31;

  const float* base = f2 + (size_t)b * 256 * 1024 + pb * 64;
#pragma unroll
  for (int k = 0; k < 16; k++) {
    int i = k * 256 + t;
    int c = i >> 4, j = i & 15;      // c = k*16 + (t>>4)
    float4 q = *(const float4*)(base + (size_t)c * 1024 + j * 4);
    ((float4*)tile)[c * 16 + j] = q;
    float s = q.x * q.x + q.y * q.y + q.z * q.z + q.w * q.w;
    for (int o = 8; o; o >>= 1) s += __shfl_down_sync(FULLMASK, s, o, 16);
    if ((lane & 15) == 0) ns[c] = s;
  }
  __syncthreads();
  g_part2[((b * 16) + pb) * 256 + t] = ns[t];
  publish(b * 3 + 2);
  wait_cnt(b * 3 + 2, 16, false);

  {
    float s = 0.f;
    const float* pp = &g_part2[b * 16 * 256 + t];
#pragma unroll 4
    for (int k = 0; k < 16; k++) s += pp[k * 256];
    ns[t] = s;
  }
  __syncthreads();
  rank_flags<256>(ns, fl);

  int p = t & 63, g = t >> 6;        // group g handles channels [g*64, g*64+64)
  float sS = 0.f, sW = 0.f;
#pragma unroll 8
  for (int cc = 0; cc < 64; cc++) {
    int c = g * 64 + cc;
    float v = tile[c * 64 + p];
    if (fl[c]) sW += v; else sS += v;
  }
  comb[g * 64 + p] = sS;
  comb[256 + g * 64 + p] = sW;
  __syncthreads();
  float ifd = 0.f;
  if (g == 0) {
    float tS = comb[p] + comb[64 + p] + comb[128 + p] + comb[192 + p];
    float tW = comb[256 + p] + comb[320 + p] + comb[384 + p] + comb[448 + p];
    float aS = 1.f / (1.f + expf(-tS * (1.f / 128.f)));
    float aW = 1.f / (1.f + expf(-tW * (1.f / 128.f)));
    float dd = aW - aS;
    ifd = dd * dd;
  }
  ifd_epilogue<false>(ifd, 0.f, 2, 0, shd);
}

// ---------------- l_main ----------------
__device__ void main_body(const float* __restrict__ pred, const int* __restrict__ tgt, int b) {
  __shared__ float sh[8];
  __shared__ float shm;
  int t = threadIdx.x;
  const float* row = pred + b * 1000;
  float m = -1e30f;
  for (int i = t; i < 1000; i += 256) m = fmaxf(m, row[i]);
  for (int o = 16; o; o >>= 1) m = fmaxf(m, __shfl_down_sync(FULLMASK, m, o));
  if ((t & 31) == 0) sh[t >> 5] = m;
  __syncthreads();
  if (t == 0) {
    float mm = sh[0];
    for (int i = 1; i < 8; i++) mm = fmaxf(mm, sh[i]);
    shm = mm;
  }
  __syncthreads();
  m = shm;
  float s = 0.f;
  for (int i = t; i < 1000; i += 256) s += expf(row[i] - m);
  for (int o = 16; o; o >>= 1) s += __shfl_down_sync(FULLMASK, s, o);
  if ((t & 31) == 0) sh[t >> 5] = s;
  __syncthreads();
  if (t == 0) {
    float ss = 0.f;
    for (int i = 0; i < 8; i++) ss += sh[i];
    int tg = tgt[b];
    double lp = (double)(row[tg] - m) - log((double)ss);
    g_main_part[b] = -lp;
    __threadfence();
    atomicAdd(&g_done, 1);
  }
}

// ---------------- final: wait 3616, reduce, reset ----------------
__device__ void final_body(float* __restrict__ out) {
  int t = threadIdx.x;
  if (t == 0) {
    volatile int* d = &g_done;
    while (*d < 3616) __nanosleep(128);
    __threadfence();
  }
  __syncthreads();
  if (t == 0) {
    double lm = 0.0;
    for (int i = 0; i < 32; i++) lm += g_main_part[i];
    double l_main = lm / 32.0;
    double ifd0 = g_acc[0] / (32.0 * 128.0 * 128.0);
    double ifd1 = g_acc[1] / (32.0 * 64.0 * 64.0);
    double ifd2 = g_acc[2] / (32.0 * 32.0 * 32.0);
    double l_ifd = (ifd0 + ifd1 + ifd2) / 3.0;
    double scr0 = g_acc[3] / (32.0 * 64.0 * 128.0 * 128.0);
    double scr1 = g_acc[4] / (32.0 * 128.0 * 64.0 * 64.0);
    double l_scr = (scr0 + scr1) / 2.0;
    double total = l_main + 0.015 * l_scr + 0.015 * l_ifd;
    out[0] = (float)total;
    out[1] = (float)l_main;
    out[2] = (float)l_scr;
    out[3] = (float)l_ifd;
  }
  __syncthreads();
  if (t < 96) g_cnt[t] = 0;
  if (t == 0) {
    g_setup_done = 0;
    g_done = 0;
    for (int i = 0; i < 8; i++) g_acc[i] = 0.0;
  }
}

// ---------------- fused kernel ----------------
// bid 0: setup | [1,2049) f0 | [2049,3073) f1 | [3073,3585) f2
// [3585,3617) main | 3617 final
__global__ void __launch_bounds__(256) k_fused(
    const float* __restrict__ pred,
    const float* __restrict__ f0,
    const float* __restrict__ f1,
    const float* __restrict__ f2,
    const int* __restrict__ tgt,
    float* __restrict__ out) {
  extern __shared__ float sm[];
  int bid = blockIdx.x;
  if (bid == 0) { setup_body(sm); return; }
  bid -= 1;
  if (bid < 2048) { body_f0(sm, f0, f2, bid >> 6, bid & 63); return; }
  bid -= 2048;
  if (bid < 1024) { body_f1(sm, f1, f2, bid >> 5, bid & 31); return; }
  bid -= 1024;
  if (bid < 512)  { body_f2(sm, f2, bid >> 4, bid & 15); return; }
  bid -= 512;
  if (bid < 32)   { main_body(pred, tgt, bid); return; }
  final_body(out);
}

extern "C" void kernel_launch(void* const* d_in, const int* in_sizes, int n_in,
                              void* d_out, int out_size) {
  const float* pred = (const float*)d_in[0];
  const float* f0   = (const float*)d_in[1];   // (32, 64, 128, 128)
  const float* f1   = (const float*)d_in[2];   // (32, 128, 64, 64)
  const float* f2   = (const float*)d_in[3];   // (32, 256, 32, 32)
  const int*   tgt  = (const int*)d_in[4];     // int32 (JAX x64 disabled)
  float* out = (float*)d_out;

  cudaFuncSetAttribute(k_fused, cudaFuncAttributeMaxDynamicSharedMemorySize, SMEM_BYTES);
  k_fused<<<3618, 256, SMEM_BYTES>>>(pred, f0, f1, f2, tgt, out);
}

// round 8
// speedup vs baseline: 1.0994x; 1.0994x over previous
#include <cuda_runtime.h>
#include <math.h>

#define FULLMASK 0xFFFFFFFFu

// ---------------- scratch (no allocations allowed) ----------------
__device__ double g_acc[8];              // 0..2 ifd0..2, 3..4 scr0..1
__device__ double g_main_part[32];
__device__ float  g_part0[32 * 64 * 64];   // [b][pb][c]
__device__ float  g_part1[32 * 32 * 128];
__device__ float  g_part2[32 * 16 * 256];
__device__ int    g_sel0[64];
__device__ int    g_sel1[128];
__device__ int    g_cnt[96];             // [b*3 + f]
__device__ int    g_setup_done;
__device__ int    g_done;                // 3584 ifd + 32 main

// ---- dynamic smem layout (floats): tile 16384 | ns 256 | sel 128 | fl 64 | shd 32 | tex 2048
#define OFF_NS   16384
#define OFF_SEL  16640
#define OFF_FL   16768
#define OFF_SHD  16832
#define OFF_TEX  16864
#define SMEM_FLOATS 18912
#define SMEM_BYTES  (SMEM_FLOATS * 4)

// ---------------- cp.async helpers ----------------
__device__ __forceinline__ unsigned smem_u32(const void* p) {
  return (unsigned)__cvta_generic_to_shared(p);
}
__device__ __forceinline__ void cp16(unsigned saddr, const void* g) {
  asm volatile("cp.async.cg.shared.global [%0], [%1], 16;" :: "r"(saddr), "l"(g));
}
__device__ __forceinline__ void cp4(unsigned saddr, const void* g) {
  asm volatile("cp.async.ca.shared.global [%0], [%1], 4;" :: "r"(saddr), "l"(g));
}
__device__ __forceinline__ void cp_wait_all() {
  asm volatile("cp.async.wait_all;" ::: "memory");
}

// ---------------- threefry2x32-20 (exact JAX semantics) ----------------
__device__ __forceinline__ void tf2x32(unsigned k0, unsigned k1,
                                       unsigned x0, unsigned x1,
                                       unsigned& o0, unsigned& o1) {
  unsigned ks2 = 0x1BD11BDAu ^ k0 ^ k1;
#define TFR(r) { x0 += x1; x1 = (x1 << (r)) | (x1 >> (32 - (r))); x1 ^= x0; }
  x0 += k0; x1 += k1;
  TFR(13) TFR(15) TFR(26) TFR(6)   x0 += k1;  x1 += ks2 + 1u;
  TFR(17) TFR(29) TFR(16) TFR(24)  x0 += ks2; x1 += k0 + 2u;
  TFR(13) TFR(15) TFR(26) TFR(6)   x0 += k0;  x1 += k1 + 3u;
  TFR(17) TFR(29) TFR(16) TFR(24)  x0 += k1;  x1 += ks2 + 4u;
  TFR(13) TFR(15) TFR(26) TFR(6)   x0 += ks2; x1 += k0 + 5u;
#undef TFR
  o0 = x0; o1 = x1;
}

__device__ __forceinline__ void warp_red(float& s) {
  for (int o = 16; o; o >>= 1) s += __shfl_down_sync(FULLMASK, s, o);
}

__device__ void setup_body(float* sm) {
  unsigned* keys = (unsigned*)(sm);
  int* perm = (int*)(sm + 256);
  int t = threadIdx.x;
#pragma unroll 1
  for (int i = 0; i < 2; i++) {
    unsigned kf0, kf1;
    tf2x32(0u, 42u, 0u, (unsigned)i, kf0, kf1);
    unsigned a0, a1, b0, b1;
    tf2x32(kf0, kf1, 0u, 2u, a0, a1);
    tf2x32(kf0, kf1, 1u, 3u, b0, b1);
    unsigned kt0 = a1, kt1 = b1;
    unsigned c0, c1, d0, d1;
    tf2x32(kt0, kt1, 0u, 2u, c0, c1);
    tf2x32(kt0, kt1, 1u, 3u, d0, d1);
    unsigned sk0 = c1, sk1 = d1;
    (void)a0; (void)b0; (void)c0; (void)d0;
    if (t < 128) {
      unsigned y0, y1;
      tf2x32(sk0, sk1, (unsigned)t, (unsigned)(t + 128), y0, y1);
      keys[t] = y0; keys[t + 128] = y1;
    }
    __syncthreads();
    unsigned my = keys[t];
    int rank = 0;
    for (int j = 0; j < 256; j++) {
      unsigned kj = keys[j];
      rank += (kj < my) || (kj == my && j < t);
    }
    perm[rank] = t;
    __syncthreads();
    if (i == 0) { if (t <  64) g_sel0[t] = perm[t]; }
    else        { if (t < 128) g_sel1[t] = perm[t]; }
    __syncthreads();
  }
  __threadfence();
  __syncthreads();
  if (t == 0) atomicExch(&g_setup_done, 1);
}

__device__ __forceinline__ void publish(int cidx) {
  __threadfence();
  __syncthreads();
  if (threadIdx.x == 0) atomicAdd(&g_cnt[cidx], 1);
}

__device__ __forceinline__ void wait_cnt(int cidx, int K) {
  if (threadIdx.x == 0) {
    volatile int* c = &g_cnt[cidx];
    while (*c < K) __nanosleep(32);
    __threadfence();
  }
  __syncthreads();
}

__device__ __forceinline__ void wait_setup() {
  if (threadIdx.x == 0) {
    volatile int* s = &g_setup_done;
    while (*s == 0) __nanosleep(32);
    __threadfence();
  }
  __syncthreads();
}

template <bool HAS_T>
__device__ __forceinline__ void ifd_epilogue(float ifd, float scr, int AI, int AS,
                                             double* shd) {
  double di = (double)ifd, ds = (double)scr;
  for (int o = 16; o; o >>= 1) {
    di += __shfl_down_sync(FULLMASK, di, o);
    if (HAS_T) ds += __shfl_down_sync(FULLMASK, ds, o);
  }
  int t = threadIdx.x, wid = t >> 5;
  if ((t & 31) == 0) { shd[wid] = di; if (HAS_T) shd[8 + wid] = ds; }
  __syncthreads();
  if (t == 0) {
    double ti = 0.0, ts = 0.0;
    for (int i = 0; i < 8; i++) { ti += shd[i]; if (HAS_T) ts += shd[8 + i]; }
    atomicAdd(&g_acc[AI], ti);
    if (HAS_T) atomicAdd(&g_acc[AS], ts);
    __threadfence();
    atomicAdd(&g_done, 1);
  }
}

template <int C>
__device__ __forceinline__ void rank_flags(const float* ns, unsigned char* fl) {
  int t = threadIdx.x;
  if (t < C) {
    float v = ns[t];
    int rank = 0;
#pragma unroll 4
    for (int j = 0; j < C; j++) {
      float nj = ns[j];
      rank += (nj > v) || (nj == v && j < t);
    }
    fl[t] = (rank < C / 2) ? (unsigned char)0 : (unsigned char)1;
  }
  __syncthreads();
}

// ---------------- feat0: C=64, tile 64ch x 256px, 64 blocks/batch ----------------
__device__ void body_f0(float* sm, const float* __restrict__ f0,
                        const float* __restrict__ f2, int b, int pb) {
  float* tile = sm;
  float* ns  = sm + OFF_NS;
  int*   sel = (int*)(sm + OFF_SEL);
  unsigned char* fl = (unsigned char*)(sm + OFF_FL);
  double* shd = (double*)(sm + OFF_SHD);
  float* tex = sm + OFF_TEX;
  int t = threadIdx.x, w = t >> 5, lane = t & 31;

  // 1. async tile load: full MLP, no reg pressure
  // tile row = 256 floats = 64 float4 slots; slot index = c*64 + j
  const float* base = f0 + (size_t)b * 64 * 16384 + pb * 256;
  unsigned tbase_s = smem_u32(tile);
#pragma unroll
  for (int k = 0; k < 16; k++) {
    int i = k * 256 + t;
    int c = i >> 6, j = i & 63;
    cp16(tbase_s + (unsigned)(c * 64 + j) * 16u, base + (size_t)c * 16384 + j * 4);
  }

  // 2. overlap: wait setup, stage sel + teacher tile (async)
  wait_setup();
  if (t < 64) sel[t] = g_sel0[t];
  __syncthreads();
  const float* tb = f2 + (size_t)b * 256 * 1024 + (pb >> 1) * 32;
  unsigned texbase_s = smem_u32(tex);
#pragma unroll
  for (int k = 0; k < 8; k++) {
    int idx = k * 256 + t;
    int c = idx >> 5, j = idx & 31;
    cp4(texbase_s + (unsigned)idx * 4u, tb + (size_t)sel[c] * 1024 + j);
  }
  cp_wait_all();
  __syncthreads();

  // 3. per-channel norm partials from smem (row-major, conflict-free)
  const float4* tile4 = (const float4*)tile;
#pragma unroll
  for (int r = 0; r < 8; r++) {
    int c = w * 8 + r;
    float4 a = tile4[c * 64 + lane];
    float4 d = tile4[c * 64 + 32 + lane];
    float s = a.x * a.x + a.y * a.y + a.z * a.z + a.w * a.w
            + d.x * d.x + d.y * d.y + d.z * d.z + d.w * d.w;
    warp_red(s);
    if (lane == 0) g_part0[((b * 64) + pb) * 64 + c] = s;
  }
  publish(b * 3 + 0);
  wait_cnt(b * 3 + 0, 64);

  // 4. global norms -> flags
  if (t < 64) {
    float s = 0.f;
    const float* pp = &g_part0[b * 64 * 64 + t];
#pragma unroll 8
    for (int k = 0; k < 64; k++) s += pp[k * 64];
    ns[t] = s;
  }
  __syncthreads();
  rank_flags<64>(ns, fl);

  // 5. phase 2 from smem
  int tcol = (t & 127) >> 2;
  float sS = 0.f, sW = 0.f, scr = 0.f;
#pragma unroll 8
  for (int c = 0; c < 64; c++) {
    float v = tile[c * 256 + t];
    float tv = tex[c * 32 + tcol];
    if (fl[c]) sW += v; else sS += v;
    float d = v - tv;
    scr += d * d;
  }
  float aS = 1.f / (1.f + expf(-sS * (1.f / 32.f)));
  float aW = 1.f / (1.f + expf(-sW * (1.f / 32.f)));
  float dd = aW - aS;
  ifd_epilogue<true>(dd * dd, scr, 0, 3, shd);
}

// ---------------- feat1: C=128, tile 128ch x 128px, 32 blocks/batch ----------------
__device__ void body_f1(float* sm, const float* __restrict__ f1,
                        const float* __restrict__ f2, int b, int pb) {
  float* tile = sm;
  float* ns  = sm + OFF_NS;
  int*   sel = (int*)(sm + OFF_SEL);
  unsigned char* fl = (unsigned char*)(sm + OFF_FL);
  double* shd = (double*)(sm + OFF_SHD);
  float* comb = sm + OFF_TEX;        // combS[128], combW[128]
  int t = threadIdx.x, w = t >> 5, lane = t & 31;

  // tile row = 128 floats = 32 float4 slots; slot = c*32 + j
  const float* base = f1 + (size_t)b * 128 * 4096 + pb * 128;
  unsigned tbase_s = smem_u32(tile);
#pragma unroll
  for (int k = 0; k < 16; k++) {
    int i = k * 256 + t;
    int c = i >> 5, j = i & 31;
    cp16(tbase_s + (unsigned)(c * 32 + j) * 16u, base + (size_t)c * 4096 + j * 4);
  }
  cp_wait_all();
  __syncthreads();

  const float4* tile4 = (const float4*)tile;
#pragma unroll
  for (int r = 0; r < 16; r++) {
    int c = w * 16 + r;
    float4 a = tile4[c * 32 + lane];
    float s = a.x * a.x + a.y * a.y + a.z * a.z + a.w * a.w;
    warp_red(s);
    if (lane == 0) g_part1[((b * 32) + pb) * 128 + c] = s;
  }
  publish(b * 3 + 1);
  wait_setup();
  wait_cnt(b * 3 + 1, 32);

  if (t < 128) {
    float s = 0.f;
    const float* pp = &g_part1[b * 32 * 128 + t];
#pragma unroll 8
    for (int k = 0; k < 32; k++) s += pp[k * 128];
    ns[t] = s;
    sel[t] = g_sel1[t];
  }
  __syncthreads();
  rank_flags<128>(ns, fl);

  int p = t & 127, g = t >> 7;       // group g: channels [g*64, g*64+64)
  int tpix = pb * 32 + ((p & 63) >> 1);
  const float* tb = f2 + (size_t)b * 256 * 1024;
  float sS = 0.f, sW = 0.f, scr = 0.f;
#pragma unroll 8
  for (int cc = 0; cc < 64; cc++) {
    int c = g * 64 + cc;
    float v = tile[c * 128 + p];
    float tv = __ldg(tb + (size_t)sel[c] * 1024 + tpix);
    if (fl[c]) sW += v; else sS += v;
    float d = v - tv;
    scr += d * d;
  }
  if (g == 1) { comb[p] = sS; comb[128 + p] = sW; }
  __syncthreads();
  float ifd = 0.f;
  if (g == 0) {
    float tS = sS + comb[p], tW = sW + comb[128 + p];
    float aS = 1.f / (1.f + expf(-tS * (1.f / 64.f)));
    float aW = 1.f / (1.f + expf(-tW * (1.f / 64.f)));
    float dd = aW - aS;
    ifd = dd * dd;
  }
  ifd_epilogue<true>(ifd, scr, 1, 4, shd);
}

// ---------------- feat2: C=256, tile 256ch x 64px, 16 blocks/batch ----------------
__device__ void body_f2(float* sm, const float* __restrict__ f2, int b, int pb) {
  float* tile = sm;
  float* ns  = sm + OFF_NS;
  unsigned char* fl = (unsigned char*)(sm + OFF_FL);
  double* shd = (double*)(sm + OFF_SHD);
  float* comb = sm + OFF_TEX;        // combS[256], combW[256]
  int t = threadIdx.x, w = t >> 5, lane = t & 31;

  // tile row = 64 floats = 16 float4 slots; slot = c*16 + j
  const float* base = f2 + (size_t)b * 256 * 1024 + pb * 64;
  unsigned tbase_s = smem_u32(tile);
#pragma unroll
  for (int k = 0; k < 16; k++) {
    int i = k * 256 + t;
    int c = i >> 4, j = i & 15;
    cp16(tbase_s + (unsigned)(c * 16 + j) * 16u, base + (size_t)c * 1024 + j * 4);
  }
  cp_wait_all();
  __syncthreads();

#pragma unroll
  for (int r = 0; r < 32; r++) {
    int c = w * 32 + r;
    float a = tile[c * 64 + lane];
    float d = tile[c * 64 + 32 + lane];
    float s = a * a + d * d;
    warp_red(s);
    if (lane == 0) g_part2[((b * 16) + pb) * 256 + c] = s;
  }
  publish(b * 3 + 2);
  wait_cnt(b * 3 + 2, 16);

  {
    float s = 0.f;
    const float* pp = &g_part2[b * 16 * 256 + t];
#pragma unroll 8
    for (int k = 0; k < 16; k++) s += pp[k * 256];
    ns[t] = s;
  }
  __syncthreads();
  rank_flags<256>(ns, fl);

  int p = t & 63, g = t >> 6;        // group g: channels [g*64, g*64+64)
  float sS = 0.f, sW = 0.f;
#pragma unroll 8
  for (int cc = 0; cc < 64; cc++) {
    int c = g * 64 + cc;
    float v = tile[c * 64 + p];
    if (fl[c]) sW += v; else sS += v;
  }
  comb[g * 64 + p] = sS;
  comb[256 + g * 64 + p] = sW;
  __syncthreads();
  float ifd = 0.f;
  if (g == 0) {
    float tS = comb[p] + comb[64 + p] + comb[128 + p] + comb[192 + p];
    float tW = comb[256 + p] + comb[320 + p] + comb[384 + p] + comb[448 + p];
    float aS = 1.f / (1.f + expf(-tS * (1.f / 128.f)));
    float aW = 1.f / (1.f + expf(-tW * (1.f / 128.f)));
    float dd = aW - aS;
    ifd = dd * dd;
  }
  ifd_epilogue<false>(ifd, 0.f, 2, 0, shd);
}

// ---------------- l_main ----------------
__device__ void main_body(const float* __restrict__ pred, const int* __restrict__ tgt, int b) {
  __shared__ float sh[8];
  __shared__ float shm;
  int t = threadIdx.x;
  const float* row = pred + b * 1000;
  float m = -1e30f;
  for (int i = t; i < 1000; i += 256) m = fmaxf(m, row[i]);
  for (int o = 16; o; o >>= 1) m = fmaxf(m, __shfl_down_sync(FULLMASK, m, o));
  if ((t & 31) == 0) sh[t >> 5] = m;
  __syncthreads();
  if (t == 0) {
    float mm = sh[0];
    for (int i = 1; i < 8; i++) mm = fmaxf(mm, sh[i]);
    shm = mm;
  }
  __syncthreads();
  m = shm;
  float s = 0.f;
  for (int i = t; i < 1000; i += 256) s += expf(row[i] - m);
  for (int o = 16; o; o >>= 1) s += __shfl_down_sync(FULLMASK, s, o);
  if ((t & 31) == 0) sh[t >> 5] = s;
  __syncthreads();
  if (t == 0) {
    float ss = 0.f;
    for (int i = 0; i < 8; i++) ss += sh[i];
    int tg = tgt[b];
    double lp = (double)(row[tg] - m) - log((double)ss);
    g_main_part[b] = -lp;
    __threadfence();
    atomicAdd(&g_done, 1);
  }
}

// ---------------- final: wait 3616, reduce, reset ----------------
__device__ void final_body(float* __restrict__ out) {
  int t = threadIdx.x;
  if (t == 0) {
    volatile int* d = &g_done;
    while (*d < 3616) __nanosleep(128);
    __threadfence();
  }
  __syncthreads();
  if (t == 0) {
    double lm = 0.0;
    for (int i = 0; i < 32; i++) lm += g_main_part[i];
    double l_main = lm / 32.0;
    double ifd0 = g_acc[0] / (32.0 * 128.0 * 128.0);
    double ifd1 = g_acc[1] / (32.0 * 64.0 * 64.0);
    double ifd2 = g_acc[2] / (32.0 * 32.0 * 32.0);
    double l_ifd = (ifd0 + ifd1 + ifd2) / 3.0;
    double scr0 = g_acc[3] / (32.0 * 64.0 * 128.0 * 128.0);
    double scr1 = g_acc[4] / (32.0 * 128.0 * 64.0 * 64.0);
    double l_scr = (scr0 + scr1) / 2.0;
    double total = l_main + 0.015 * l_scr + 0.015 * l_ifd;
    out[0] = (float)total;
    out[1] = (float)l_main;
    out[2] = (float)l_scr;
    out[3] = (float)l_ifd;
  }
  __syncthreads();
  if (t < 96) g_cnt[t] = 0;
  if (t == 0) {
    g_setup_done = 0;
    g_done = 0;
    for (int i = 0; i < 8; i++) g_acc[i] = 0.0;
  }
}

// ---------------- fused kernel ----------------
__global__ void __launch_bounds__(256, 3) k_fused(
    const float* __restrict__ pred,
    const float* __restrict__ f0,
    const float* __restrict__ f1,
    const float* __restrict__ f2,
    const int* __restrict__ tgt,
    float* __restrict__ out) {
  extern __shared__ float sm[];
  int bid = blockIdx.x;
  if (bid == 0) { setup_body(sm); return; }
  bid -= 1;
  if (bid < 2048) { body_f0(sm, f0, f2, bid >> 6, bid & 63); return; }
  bid -= 2048;
  if (bid < 1024) { body_f1(sm, f1, f2, bid >> 5, bid & 31); return; }
  bid -= 1024;
  if (bid < 512)  { body_f2(sm, f2, bid >> 4, bid & 15); return; }
  bid -= 512;
  if (bid < 32)   { main_body(pred, tgt, bid); return; }
  final_body(out);
}

extern "C" void kernel_launch(void* const* d_in, const int* in_sizes, int n_in,
                              void* d_out, int out_size) {
  const float* pred = (const float*)d_in[0];
  const float* f0   = (const float*)d_in[1];   // (32, 64, 128, 128)
  const float* f1   = (const float*)d_in[2];   // (32, 128, 64, 64)
  const float* f2   = (const float*)d_in[3];   // (32, 256, 32, 32)
  const int*   tgt  = (const int*)d_in[4];     // int32 (JAX x64 disabled)
  float* out = (float*)d_out;

  cudaFuncSetAttribute(k_fused, cudaFuncAttributeMaxDynamicSharedMemorySize, SMEM_BYTES);
  k_fused<<<3618, 256, SMEM_BYTES>>>(pred, f0, f1, f2, tgt, out);
}

// round 9
// speedup vs baseline: 1.8580x; 1.6900x over previous
#include <cuda_runtime.h>
#include <math.h>

#define FULLMASK 0xFFFFFFFFu

// ---------------- scratch (no allocations allowed) ----------------
__device__ double g_acc[8];            // 0..2 ifd0..2, 3..4 scr0..1
__device__ double g_main_part[32];
__device__ float  g_np0[32 * 32 * 64];   // norm partials [b][strip][c]
__device__ float  g_np1[32 * 16 * 128];
__device__ float  g_np2[32 * 8 * 256];
__device__ float  g_ps0[32 * 16384];     // per-pixel all-channel sums
__device__ float  g_ps1[32 * 4096];
__device__ float  g_ps2[32 * 1024];

struct Sel { int s0[64]; int s1[128]; };

__device__ __forceinline__ void warp_red(float& s) {
  for (int o = 16; o; o >>= 1) s += __shfl_down_sync(FULLMASK, s, o);
}

__device__ __forceinline__ void block_add_double(float val, int slot, double* shd) {
  double d = (double)val;
  for (int o = 16; o; o >>= 1) d += __shfl_down_sync(FULLMASK, d, o);
  int t = threadIdx.x, w = t >> 5;
  if ((t & 31) == 0) shd[w] = d;
  __syncthreads();
  if (t == 0) {
    double s = 0.0;
    for (int i = 0; i < 8; i++) s += shd[i];
    atomicAdd(&g_acc[slot], s);
  }
}

// =========================== PASS A ===========================
// one read of all features: norm partials + per-pixel sums + SCR

// f0: block=(b, strip s of 512px = 4 rows of 128). 8 warps x 8 channels.
__device__ void passa_f0(float* buf, double* shd, const float* __restrict__ f0,
                         const float* __restrict__ f2, const Sel& sel, int b, int s) {
  int t = threadIdx.x, w = t >> 5, lane = t & 31;
  const float* base = f0 + (size_t)b * 64 * 16384 + s * 512;
  const float* tb = f2 + (size_t)b * 256 * 1024 + s * 32;  // texel row == s
  float4 ps[4];
#pragma unroll
  for (int q = 0; q < 4; q++) ps[q] = make_float4(0.f, 0.f, 0.f, 0.f);
  float n[8];
  float scr = 0.f;
#pragma unroll
  for (int r = 0; r < 8; r++) {
    int c = w * 8 + r;
    const float4* pc = (const float4*)(base + (size_t)c * 16384);
    float tv = tb[(size_t)sel.s0[c] * 1024 + lane];
    float nn = 0.f;
#pragma unroll
    for (int q = 0; q < 4; q++) {
      float4 v = pc[lane + 32 * q];
      ps[q].x += v.x; ps[q].y += v.y; ps[q].z += v.z; ps[q].w += v.w;
      nn += v.x * v.x + v.y * v.y + v.z * v.z + v.w * v.w;
      float d0 = v.x - tv, d1 = v.y - tv, d2 = v.z - tv, d3 = v.w - tv;
      scr += d0 * d0 + d1 * d1 + d2 * d2 + d3 * d3;
    }
    n[r] = nn;
  }
#pragma unroll
  for (int r = 0; r < 8; r++) {
    float nn = n[r];
    warp_red(nn);
    if (lane == 0) g_np0[((b * 32 + s) * 64) + w * 8 + r] = nn;
  }
  // cross-warp pixsum: stage per-warp, then sum in fixed order
  float4* b4 = (float4*)(buf + w * 512);
#pragma unroll
  for (int q = 0; q < 4; q++) b4[lane + 32 * q] = ps[q];
  __syncthreads();
  float* gp = g_ps0 + (size_t)b * 16384 + s * 512;
  for (int p = t; p < 512; p += 256) {
    float ss = 0.f;
#pragma unroll
    for (int w2 = 0; w2 < 8; w2++) ss += buf[w2 * 512 + p];
    gp[p] = ss;
  }
  block_add_double(scr, 3, shd);
}

// f1: block=(b, strip s of 256px = 4 rows of 64). 8 warps x 16 channels.
__device__ void passa_f1(float* buf, double* shd, const float* __restrict__ f1,
                         const float* __restrict__ f2, const Sel& sel, int b, int s) {
  int t = threadIdx.x, w = t >> 5, lane = t & 31;
  const float* base = f1 + (size_t)b * 128 * 4096 + s * 256;
  const float* tb = f2 + (size_t)b * 256 * 1024;
  int tcol = (2 * lane) & 31;
  float4 ps0 = make_float4(0.f, 0.f, 0.f, 0.f), ps1 = ps0;
  float n[16];
  float scr = 0.f;
#pragma unroll
  for (int r = 0; r < 16; r++) {
    int c = w * 16 + r;
    const float4* pc = (const float4*)(base + (size_t)c * 4096);
    const float* tc = tb + (size_t)sel.s1[c] * 1024;
    float2 t0 = *(const float2*)(tc + (2 * s) * 32 + tcol);
    float2 t1 = *(const float2*)(tc + (2 * s + 1) * 32 + tcol);
    float4 v0 = pc[lane];
    float4 v1 = pc[lane + 32];
    ps0.x += v0.x; ps0.y += v0.y; ps0.z += v0.z; ps0.w += v0.w;
    ps1.x += v1.x; ps1.y += v1.y; ps1.z += v1.z; ps1.w += v1.w;
    n[r] = v0.x * v0.x + v0.y * v0.y + v0.z * v0.z + v0.w * v0.w
         + v1.x * v1.x + v1.y * v1.y + v1.z * v1.z + v1.w * v1.w;
    float a0 = v0.x - t0.x, a1 = v0.y - t0.x, a2 = v0.z - t0.y, a3 = v0.w - t0.y;
    float b0 = v1.x - t1.x, b1 = v1.y - t1.x, b2 = v1.z - t1.y, b3 = v1.w - t1.y;
    scr += a0 * a0 + a1 * a1 + a2 * a2 + a3 * a3
         + b0 * b0 + b1 * b1 + b2 * b2 + b3 * b3;
  }
#pragma unroll
  for (int r = 0; r < 16; r++) {
    float nn = n[r];
    warp_red(nn);
    if (lane == 0) g_np1[((b * 16 + s) * 128) + w * 16 + r] = nn;
  }
  float4* b4 = (float4*)(buf + w * 256);
  b4[lane] = ps0;
  b4[lane + 32] = ps1;
  __syncthreads();
  float* gp = g_ps1 + (size_t)b * 4096 + s * 256;
  if (t < 256) {
    float ss = 0.f;
#pragma unroll
    for (int w2 = 0; w2 < 8; w2++) ss += buf[w2 * 256 + t];
    gp[t] = ss;
  }
  block_add_double(scr, 4, shd);
}

// f2: block=(b, strip s of 128px). 8 warps x 32 channels. no teacher.
__device__ void passa_f2(float* buf, const float* __restrict__ f2, int b, int s) {
  int t = threadIdx.x, w = t >> 5, lane = t & 31;
  const float* base = f2 + (size_t)b * 256 * 1024 + s * 128;
  float4 ps = make_float4(0.f, 0.f, 0.f, 0.f);
#pragma unroll
  for (int g = 0; g < 4; g++) {
    float n[8];
#pragma unroll
    for (int r = 0; r < 8; r++) {
      int c = w * 32 + g * 8 + r;
      float4 v = ((const float4*)(base + (size_t)c * 1024))[lane];
      ps.x += v.x; ps.y += v.y; ps.z += v.z; ps.w += v.w;
      n[r] = v.x * v.x + v.y * v.y + v.z * v.z + v.w * v.w;
    }
#pragma unroll
    for (int r = 0; r < 8; r++) {
      float nn = n[r];
      warp_red(nn);
      if (lane == 0) g_np2[((b * 8 + s) * 256) + w * 32 + g * 8 + r] = nn;
    }
  }
  float4* b4 = (float4*)(buf + w * 128);
  b4[lane] = ps;
  __syncthreads();
  float* gp = g_ps2 + (size_t)b * 1024 + s * 128;
  if (t < 128) {
    float ss = 0.f;
#pragma unroll
    for (int w2 = 0; w2 < 8; w2++) ss += buf[w2 * 128 + t];
    gp[t] = ss;
  }
}

// l_main
__device__ void main_body(const float* __restrict__ pred, const int* __restrict__ tgt, int b) {
  __shared__ float sh[8];
  __shared__ float shm;
  int t = threadIdx.x;
  const float* row = pred + b * 1000;
  float m = -1e30f;
  for (int i = t; i < 1000; i += 256) m = fmaxf(m, row[i]);
  for (int o = 16; o; o >>= 1) m = fmaxf(m, __shfl_down_sync(FULLMASK, m, o));
  if ((t & 31) == 0) sh[t >> 5] = m;
  __syncthreads();
  if (t == 0) {
    float mm = sh[0];
    for (int i = 1; i < 8; i++) mm = fmaxf(mm, sh[i]);
    shm = mm;
  }
  __syncthreads();
  m = shm;
  float s = 0.f;
  for (int i = t; i < 1000; i += 256) s += expf(row[i] - m);
  for (int o = 16; o; o >>= 1) s += __shfl_down_sync(FULLMASK, s, o);
  if ((t & 31) == 0) sh[t >> 5] = s;
  __syncthreads();
  if (t == 0) {
    float ss = 0.f;
    for (int i = 0; i < 8; i++) ss += sh[i];
    int tg = tgt[b];
    double lp = (double)(row[tg] - m) - log((double)ss);
    g_main_part[b] = -lp;
  }
}

__global__ void __launch_bounds__(256) k_passA(
    const float* __restrict__ pred, const float* __restrict__ f0,
    const float* __restrict__ f1, const float* __restrict__ f2,
    const int* __restrict__ tgt, Sel sel) {
  __shared__ __align__(16) float buf[8 * 512];
  __shared__ double shd[8];
  int bid = blockIdx.x;
  if (bid < 1024) { passa_f0(buf, shd, f0, f2, sel, bid >> 5, bid & 31); return; }
  bid -= 1024;
  if (bid < 512)  { passa_f1(buf, shd, f1, f2, sel, bid >> 4, bid & 15); return; }
  bid -= 512;
  if (bid < 256)  { passa_f2(buf, f2, bid >> 3, bid & 7); return; }
  bid -= 256;
  main_body(pred, tgt, bid);
}

// =========================== PASS B ===========================
// IFD only: read strong half, weak = pixsum - strong

template <int C>
__device__ __forceinline__ void rank_flags(const float* ns, unsigned char* fl) {
  int t = threadIdx.x;
  if (t < C) {
    float v = ns[t];
    int rank = 0;
#pragma unroll 4
    for (int j = 0; j < C; j++) {
      float nj = ns[j];
      rank += (nj > v) || (nj == v && j < t);   // argsort(-norm), stable
    }
    fl[t] = (rank < C / 2) ? (unsigned char)0 : (unsigned char)1;
  }
  __syncthreads();
}

__device__ __forceinline__ float sigmoidf_(float x) { return 1.f / (1.f + expf(-x)); }

// f0: 16 blocks/batch, vec4 (1024 px/block)
__device__ void passb_f0(const float* __restrict__ f0, int b, int pb,
                         float* ns, unsigned char* fl, double* shd) {
  int t = threadIdx.x;
  if (t < 64) {
    float s = 0.f;
    const float* pp = g_np0 + b * 32 * 64 + t;
#pragma unroll 8
    for (int k = 0; k < 32; k++) s += pp[k * 64];
    ns[t] = s;
  }
  __syncthreads();
  rank_flags<64>(ns, fl);
  int p0 = pb * 1024 + t * 4;
  const float* xb = f0 + (size_t)b * 64 * 16384 + p0;
  float s0 = 0.f, s1 = 0.f, s2 = 0.f, s3 = 0.f;
#pragma unroll 8
  for (int c = 0; c < 64; c++) {
    if (!fl[c]) {
      float4 v = *(const float4*)(xb + (size_t)c * 16384);
      s0 += v.x; s1 += v.y; s2 += v.z; s3 += v.w;
    }
  }
  float4 pa = *(const float4*)(g_ps0 + (size_t)b * 16384 + p0);
  const float inv = 1.f / 32.f;
  float d0 = sigmoidf_((pa.x - s0) * inv) - sigmoidf_(s0 * inv);
  float d1 = sigmoidf_((pa.y - s1) * inv) - sigmoidf_(s1 * inv);
  float d2 = sigmoidf_((pa.z - s2) * inv) - sigmoidf_(s2 * inv);
  float d3 = sigmoidf_((pa.w - s3) * inv) - sigmoidf_(s3 * inv);
  block_add_double(d0 * d0 + d1 * d1 + d2 * d2 + d3 * d3, 0, shd);
}

// f1: 8 blocks/batch, vec2 (512 px/block)
__device__ void passb_f1(const float* __restrict__ f1, int b, int pb,
                         float* ns, unsigned char* fl, double* shd) {
  int t = threadIdx.x;
  if (t < 128) {
    float s = 0.f;
    const float* pp = g_np1 + b * 16 * 128 + t;
#pragma unroll 8
    for (int k = 0; k < 16; k++) s += pp[k * 128];
    ns[t] = s;
  }
  __syncthreads();
  rank_flags<128>(ns, fl);
  int p0 = pb * 512 + t * 2;
  const float* xb = f1 + (size_t)b * 128 * 4096 + p0;
  float s0 = 0.f, s1 = 0.f;
#pragma unroll 8
  for (int c = 0; c < 128; c++) {
    if (!fl[c]) {
      float2 v = *(const float2*)(xb + (size_t)c * 4096);
      s0 += v.x; s1 += v.y;
    }
  }
  float2 pa = *(const float2*)(g_ps1 + (size_t)b * 4096 + p0);
  const float inv = 1.f / 64.f;
  float d0 = sigmoidf_((pa.x - s0) * inv) - sigmoidf_(s0 * inv);
  float d1 = sigmoidf_((pa.y - s1) * inv) - sigmoidf_(s1 * inv);
  block_add_double(d0 * d0 + d1 * d1, 1, shd);
}

// f2: 4 blocks/batch, vec1 (256 px/block)
__device__ void passb_f2(const float* __restrict__ f2, int b, int pb,
                         float* ns, unsigned char* fl, double* shd) {
  int t = threadIdx.x;
  {
    float s = 0.f;
    const float* pp = g_np2 + b * 8 * 256 + t;
#pragma unroll 8
    for (int k = 0; k < 8; k++) s += pp[k * 256];
    ns[t] = s;
  }
  __syncthreads();
  rank_flags<256>(ns, fl);
  int p0 = pb * 256 + t;
  const float* xb = f2 + (size_t)b * 256 * 1024 + p0;
  float s0 = 0.f;
#pragma unroll 8
  for (int c = 0; c < 256; c++) {
    if (!fl[c]) s0 += xb[(size_t)c * 1024];
  }
  float pa = g_ps2[(size_t)b * 1024 + p0];
  const float inv = 1.f / 128.f;
  float d0 = sigmoidf_((pa - s0) * inv) - sigmoidf_(s0 * inv);
  block_add_double(d0 * d0, 2, shd);
}

__global__ void __launch_bounds__(256) k_passB(
    const float* __restrict__ f0, const float* __restrict__ f1,
    const float* __restrict__ f2) {
  __shared__ float ns[256];
  __shared__ unsigned char fl[256];
  __shared__ double shd[8];
  int bid = blockIdx.x;
  // f2 first (still warm in L2 from passA), then f1, then f0
  if (bid < 128) { passb_f2(f2, bid >> 2, bid & 3, ns, fl, shd); return; }
  bid -= 128;
  if (bid < 256) { passb_f1(f1, bid >> 3, bid & 7, ns, fl, shd); return; }
  bid -= 256;
  passb_f0(f0, bid >> 4, bid & 15, ns, fl, shd);
}

// =========================== FINAL ===========================
__global__ void k_final(float* __restrict__ out) {
  if (threadIdx.x == 0) {
    double lm = 0.0;
    for (int i = 0; i < 32; i++) lm += g_main_part[i];
    double l_main = lm / 32.0;
    double ifd0 = g_acc[0] / (32.0 * 128.0 * 128.0);
    double ifd1 = g_acc[1] / (32.0 * 64.0 * 64.0);
    double ifd2 = g_acc[2] / (32.0 * 32.0 * 32.0);
    double l_ifd = (ifd0 + ifd1 + ifd2) / 3.0;
    double scr0 = g_acc[3] / (32.0 * 64.0 * 128.0 * 128.0);
    double scr1 = g_acc[4] / (32.0 * 128.0 * 64.0 * 64.0);
    double l_scr = (scr0 + scr1) / 2.0;
    double total = l_main + 0.015 * l_scr + 0.015 * l_ifd;
    out[0] = (float)total;
    out[1] = (float)l_main;
    out[2] = (float)l_scr;
    out[3] = (float)l_ifd;
    for (int i = 0; i < 8; i++) g_acc[i] = 0.0;   // reset for next replay
  }
}

// =========================== HOST: constant channel permutations ===========================
static void tf_h(unsigned k0, unsigned k1, unsigned x0, unsigned x1,
                 unsigned* o0, unsigned* o1) {
  unsigned ks2 = 0x1BD11BDAu ^ k0 ^ k1;
#define TFRH(r) { x0 += x1; x1 = (x1 << (r)) | (x1 >> (32 - (r))); x1 ^= x0; }
  x0 += k0; x1 += k1;
  TFRH(13) TFRH(15) TFRH(26) TFRH(6)   x0 += k1;  x1 += ks2 + 1u;
  TFRH(17) TFRH(29) TFRH(16) TFRH(24)  x0 += ks2; x1 += k0 + 2u;
  TFRH(13) TFRH(15) TFRH(26) TFRH(6)   x0 += k0;  x1 += k1 + 3u;
  TFRH(17) TFRH(29) TFRH(16) TFRH(24)  x0 += k1;  x1 += ks2 + 4u;
  TFRH(13) TFRH(15) TFRH(26) TFRH(6)   x0 += ks2; x1 += k0 + 5u;
#undef TFRH
  *o0 = x0; *o1 = x1;
}

static void compute_sel(Sel* S) {
  for (int i = 0; i < 2; i++) {
    unsigned kf0, kf1, a0, a1, b0, b1, c0, c1, d0, d1;
    tf_h(0u, 42u, 0u, (unsigned)i, &kf0, &kf1);
    tf_h(kf0, kf1, 0u, 2u, &a0, &a1);
    tf_h(kf0, kf1, 1u, 3u, &b0, &b1);
    unsigned kt0 = a1, kt1 = b1;
    tf_h(kt0, kt1, 0u, 2u, &c0, &c1);
    tf_h(kt0, kt1, 1u, 3u, &d0, &d1);
    unsigned sk0 = c1, sk1 = d1;
    (void)a0; (void)b0; (void)c0; (void)d0;
    unsigned keys[256];
    for (int j = 0; j < 128; j++) {
      unsigned y0, y1;
      tf_h(sk0, sk1, (unsigned)j, (unsigned)(j + 128), &y0, &y1);
      keys[j] = y0; keys[j + 128] = y1;
    }
    int perm[256];
    for (int t = 0; t < 256; t++) {
      unsigned my = keys[t];
      int rank = 0;
      for (int j = 0; j < 256; j++) {
        unsigned kj = keys[j];
        rank += (kj < my) || (kj == my && j < t);
      }
      perm[rank] = t;
    }
    if (i == 0) { for (int t = 0; t < 64;  t++) S->s0[t] = perm[t]; }
    else        { for (int t = 0; t < 128; t++) S->s1[t] = perm[t]; }
  }
}

extern "C" void kernel_launch(void* const* d_in, const int* in_sizes, int n_in,
                              void* d_out, int out_size) {
  const float* pred = (const float*)d_in[0];
  const float* f0   = (const float*)d_in[1];   // (32, 64, 128, 128)
  const float* f1   = (const float*)d_in[2];   // (32, 128, 64, 64)
  const float* f2   = (const float*)d_in[3];   // (32, 256, 32, 32)
  const int*   tgt  = (const int*)d_in[4];     // int32 (JAX x64 disabled)
  float* out = (float*)d_out;

  Sel sel;
  compute_sel(&sel);                            // deterministic constants

  k_passA<<<1824, 256>>>(pred, f0, f1, f2, tgt, sel);  // 1024 f0 + 512 f1 + 256 f2 + 32 main
  k_passB<<<896, 256>>>(f0, f1, f2);                   // 128 f2 + 256 f1 + 512 f0
  k_final<<<1, 32>>>(out);
}

// round 10
// speedup vs baseline: 2.2706x; 1.2221x over previous
#include <cuda_runtime.h>
#include <math.h>

#define FULLMASK 0xFFFFFFFFu

// ---------------- scratch (no allocations allowed) ----------------
__device__ double g_acc[8];            // 0..2 ifd0..2, 3..4 scr0..1
__device__ double g_main_part[32];
__device__ float  g_np0[32 * 32 * 64];   // norm partials [b][strip][c]
__device__ float  g_np1[32 * 16 * 128];
__device__ float  g_np2[32 * 8 * 256];
__device__ float  g_ps0[32 * 16384];     // per-pixel all-channel sums
__device__ float  g_ps1[32 * 4096];
__device__ float  g_ps2[32 * 1024];

struct Sel { int s0[64]; int s1[128]; };

__device__ __forceinline__ void warp_red(float& s) {
  for (int o = 16; o; o >>= 1) s += __shfl_down_sync(FULLMASK, s, o);
}

__device__ __forceinline__ void block_add_double(float val, int slot, double* shd) {
  double d = (double)val;
  for (int o = 16; o; o >>= 1) d += __shfl_down_sync(FULLMASK, d, o);
  int t = threadIdx.x, w = t >> 5;
  if ((t & 31) == 0) shd[w] = d;
  __syncthreads();
  if (t == 0) {
    double s = 0.0;
    for (int i = 0; i < 8; i++) s += shd[i];
    atomicAdd(&g_acc[slot], s);
  }
}

// =========================== PASS A ===========================
// one read of all features: norm partials + per-pixel sums + SCR

// f0: block=(b, strip s of 512px = 4 rows of 128). 8 warps x 8 channels.
__device__ void passa_f0(float* buf, double* shd, const float* __restrict__ f0,
                         const float* __restrict__ f2, const Sel& sel, int b, int s) {
  int t = threadIdx.x, w = t >> 5, lane = t & 31;
  const float* base = f0 + (size_t)b * 64 * 16384 + s * 512;
  const float* tb = f2 + (size_t)b * 256 * 1024 + s * 32;  // texel row == s
  float4 ps[4];
#pragma unroll
  for (int q = 0; q < 4; q++) ps[q] = make_float4(0.f, 0.f, 0.f, 0.f);
  float n[8];
  float scr = 0.f;
#pragma unroll
  for (int r = 0; r < 8; r++) {
    int c = w * 8 + r;
    const float4* pc = (const float4*)(base + (size_t)c * 16384);
    float tv = tb[(size_t)sel.s0[c] * 1024 + lane];
    float nn = 0.f;
#pragma unroll
    for (int q = 0; q < 4; q++) {
      float4 v = pc[lane + 32 * q];
      ps[q].x += v.x; ps[q].y += v.y; ps[q].z += v.z; ps[q].w += v.w;
      nn += v.x * v.x + v.y * v.y + v.z * v.z + v.w * v.w;
      float d0 = v.x - tv, d1 = v.y - tv, d2 = v.z - tv, d3 = v.w - tv;
      scr += d0 * d0 + d1 * d1 + d2 * d2 + d3 * d3;
    }
    n[r] = nn;
  }
#pragma unroll
  for (int r = 0; r < 8; r++) {
    float nn = n[r];
    warp_red(nn);
    if (lane == 0) g_np0[((b * 32 + s) * 64) + w * 8 + r] = nn;
  }
  // cross-warp pixsum: stage per-warp, then sum in fixed order
  float4* b4 = (float4*)(buf + w * 512);
#pragma unroll
  for (int q = 0; q < 4; q++) b4[lane + 32 * q] = ps[q];
  __syncthreads();
  float* gp = g_ps0 + (size_t)b * 16384 + s * 512;
  for (int p = t; p < 512; p += 256) {
    float ss = 0.f;
#pragma unroll
    for (int w2 = 0; w2 < 8; w2++) ss += buf[w2 * 512 + p];
    gp[p] = ss;
  }
  block_add_double(scr, 3, shd);
}

// f1: block=(b, strip s of 256px = 4 rows of 64). 8 warps x 16 channels.
__device__ void passa_f1(float* buf, double* shd, const float* __restrict__ f1,
                         const float* __restrict__ f2, const Sel& sel, int b, int s) {
  int t = threadIdx.x, w = t >> 5, lane = t & 31;
  const float* base = f1 + (size_t)b * 128 * 4096 + s * 256;
  const float* tb = f2 + (size_t)b * 256 * 1024;
  int tcol = (2 * lane) & 31;
  float4 ps0 = make_float4(0.f, 0.f, 0.f, 0.f), ps1 = ps0;
  float n[16];
  float scr = 0.f;
#pragma unroll
  for (int r = 0; r < 16; r++) {
    int c = w * 16 + r;
    const float4* pc = (const float4*)(base + (size_t)c * 4096);
    const float* tc = tb + (size_t)sel.s1[c] * 1024;
    float2 t0 = *(const float2*)(tc + (2 * s) * 32 + tcol);
    float2 t1 = *(const float2*)(tc + (2 * s + 1) * 32 + tcol);
    float4 v0 = pc[lane];
    float4 v1 = pc[lane + 32];
    ps0.x += v0.x; ps0.y += v0.y; ps0.z += v0.z; ps0.w += v0.w;
    ps1.x += v1.x; ps1.y += v1.y; ps1.z += v1.z; ps1.w += v1.w;
    n[r] = v0.x * v0.x + v0.y * v0.y + v0.z * v0.z + v0.w * v0.w
         + v1.x * v1.x + v1.y * v1.y + v1.z * v1.z + v1.w * v1.w;
    float a0 = v0.x - t0.x, a1 = v0.y - t0.x, a2 = v0.z - t0.y, a3 = v0.w - t0.y;
    float b0 = v1.x - t1.x, b1 = v1.y - t1.x, b2 = v1.z - t1.y, b3 = v1.w - t1.y;
    scr += a0 * a0 + a1 * a1 + a2 * a2 + a3 * a3
         + b0 * b0 + b1 * b1 + b2 * b2 + b3 * b3;
  }
#pragma unroll
  for (int r = 0; r < 16; r++) {
    float nn = n[r];
    warp_red(nn);
    if (lane == 0) g_np1[((b * 16 + s) * 128) + w * 16 + r] = nn;
  }
  float4* b4 = (float4*)(buf + w * 256);
  b4[lane] = ps0;
  b4[lane + 32] = ps1;
  __syncthreads();
  float* gp = g_ps1 + (size_t)b * 4096 + s * 256;
  if (t < 256) {
    float ss = 0.f;
#pragma unroll
    for (int w2 = 0; w2 < 8; w2++) ss += buf[w2 * 256 + t];
    gp[t] = ss;
  }
  block_add_double(scr, 4, shd);
}

// f2: block=(b, strip s of 128px). 8 warps x 32 channels. no teacher.
__device__ void passa_f2(float* buf, const float* __restrict__ f2, int b, int s) {
  int t = threadIdx.x, w = t >> 5, lane = t & 31;
  const float* base = f2 + (size_t)b * 256 * 1024 + s * 128;
  float4 ps = make_float4(0.f, 0.f, 0.f, 0.f);
#pragma unroll
  for (int g = 0; g < 4; g++) {
    float n[8];
#pragma unroll
    for (int r = 0; r < 8; r++) {
      int c = w * 32 + g * 8 + r;
      float4 v = ((const float4*)(base + (size_t)c * 1024))[lane];
      ps.x += v.x; ps.y += v.y; ps.z += v.z; ps.w += v.w;
      n[r] = v.x * v.x + v.y * v.y + v.z * v.z + v.w * v.w;
    }
#pragma unroll
    for (int r = 0; r < 8; r++) {
      float nn = n[r];
      warp_red(nn);
      if (lane == 0) g_np2[((b * 8 + s) * 256) + w * 32 + g * 8 + r] = nn;
    }
  }
  float4* b4 = (float4*)(buf + w * 128);
  b4[lane] = ps;
  __syncthreads();
  float* gp = g_ps2 + (size_t)b * 1024 + s * 128;
  if (t < 128) {
    float ss = 0.f;
#pragma unroll
    for (int w2 = 0; w2 < 8; w2++) ss += buf[w2 * 128 + t];
    gp[t] = ss;
  }
}

// l_main
__device__ void main_body(const float* __restrict__ pred, const int* __restrict__ tgt, int b) {
  __shared__ float sh[8];
  __shared__ float shm;
  int t = threadIdx.x;
  const float* row = pred + b * 1000;
  float m = -1e30f;
  for (int i = t; i < 1000; i += 256) m = fmaxf(m, row[i]);
  for (int o = 16; o; o >>= 1) m = fmaxf(m, __shfl_down_sync(FULLMASK, m, o));
  if ((t & 31) == 0) sh[t >> 5] = m;
  __syncthreads();
  if (t == 0) {
    float mm = sh[0];
    for (int i = 1; i < 8; i++) mm = fmaxf(mm, sh[i]);
    shm = mm;
  }
  __syncthreads();
  m = shm;
  float s = 0.f;
  for (int i = t; i < 1000; i += 256) s += expf(row[i] - m);
  for (int o = 16; o; o >>= 1) s += __shfl_down_sync(FULLMASK, s, o);
  if ((t & 31) == 0) sh[t >> 5] = s;
  __syncthreads();
  if (t == 0) {
    float ss = 0.f;
    for (int i = 0; i < 8; i++) ss += sh[i];
    int tg = tgt[b];
    double lp = (double)(row[tg] - m) - log((double)ss);
    g_main_part[b] = -lp;
  }
}

__global__ void __launch_bounds__(256) k_passA(
    const float* __restrict__ pred, const float* __restrict__ f0,
    const float* __restrict__ f1, const float* __restrict__ f2,
    const int* __restrict__ tgt, Sel sel) {
  __shared__ __align__(16) float buf[8 * 512];
  __shared__ double shd[8];
  int bid = blockIdx.x;
  if (bid < 1024) { passa_f0(buf, shd, f0, f2, sel, bid >> 5, bid & 31); return; }
  bid -= 1024;
  if (bid < 512)  { passa_f1(buf, shd, f1, f2, sel, bid >> 4, bid & 15); return; }
  bid -= 512;
  if (bid < 256)  { passa_f2(buf, f2, bid >> 3, bid & 7); return; }
  bid -= 256;
  main_body(pred, tgt, bid);
}

// =========================== PASS B ===========================
// IFD only: read strong half via compacted index list, weak = pixsum - strong

// rank < C/2  <=>  strong; rank is a permutation, so sidx[rank] = channel
// gives a dense, deterministic strong-channel list with zero extra work.
template <int C>
__device__ __forceinline__ void rank_strong(const float* ns, int* sidx) {
  int t = threadIdx.x;
  if (t < C) {
    float v = ns[t];
    int rank = 0;
#pragma unroll 4
    for (int j = 0; j < C; j++) {
      float nj = ns[j];
      rank += (nj > v) || (nj == v && j < t);   // argsort(-norm), stable
    }
    if (rank < C / 2) sidx[rank] = t;
  }
  __syncthreads();
}

__device__ __forceinline__ float sigmoidf_(float x) { return 1.f / (1.f + expf(-x)); }

// f0: 16 blocks/batch, vec4 (1024 px/block), 32 strong planes
__device__ void passb_f0(const float* __restrict__ f0, int b, int pb,
                         float* ns, int* sidx, double* shd) {
  int t = threadIdx.x;
  if (t < 64) {
    float s = 0.f;
    const float* pp = g_np0 + b * 32 * 64 + t;
#pragma unroll 8
    for (int k = 0; k < 32; k++) s += pp[k * 64];
    ns[t] = s;
  }
  __syncthreads();
  rank_strong<64>(ns, sidx);
  int p0 = pb * 1024 + t * 4;
  const float* xb = f0 + (size_t)b * 64 * 16384 + p0;
  float s0 = 0.f, s1 = 0.f, s2 = 0.f, s3 = 0.f;
#pragma unroll 8
  for (int k = 0; k < 32; k++) {
    float4 v = *(const float4*)(xb + (size_t)sidx[k] * 16384);
    s0 += v.x; s1 += v.y; s2 += v.z; s3 += v.w;
  }
  float4 pa = *(const float4*)(g_ps0 + (size_t)b * 16384 + p0);
  const float inv = 1.f / 32.f;
  float d0 = sigmoidf_((pa.x - s0) * inv) - sigmoidf_(s0 * inv);
  float d1 = sigmoidf_((pa.y - s1) * inv) - sigmoidf_(s1 * inv);
  float d2 = sigmoidf_((pa.z - s2) * inv) - sigmoidf_(s2 * inv);
  float d3 = sigmoidf_((pa.w - s3) * inv) - sigmoidf_(s3 * inv);
  block_add_double(d0 * d0 + d1 * d1 + d2 * d2 + d3 * d3, 0, shd);
}

// f1: 8 blocks/batch, vec2 (512 px/block), 64 strong planes
__device__ void passb_f1(const float* __restrict__ f1, int b, int pb,
                         float* ns, int* sidx, double* shd) {
  int t = threadIdx.x;
  if (t < 128) {
    float s = 0.f;
    const float* pp = g_np1 + b * 16 * 128 + t;
#pragma unroll 8
    for (int k = 0; k < 16; k++) s += pp[k * 128];
    ns[t] = s;
  }
  __syncthreads();
  rank_strong<128>(ns, sidx);
  int p0 = pb * 512 + t * 2;
  const float* xb = f1 + (size_t)b * 128 * 4096 + p0;
  float s0 = 0.f, s1 = 0.f;
#pragma unroll 8
  for (int k = 0; k < 64; k++) {
    float2 v = *(const float2*)(xb + (size_t)sidx[k] * 4096);
    s0 += v.x; s1 += v.y;
  }
  float2 pa = *(const float2*)(g_ps1 + (size_t)b * 4096 + p0);
  const float inv = 1.f / 64.f;
  float d0 = sigmoidf_((pa.x - s0) * inv) - sigmoidf_(s0 * inv);
  float d1 = sigmoidf_((pa.y - s1) * inv) - sigmoidf_(s1 * inv);
  block_add_double(d0 * d0 + d1 * d1, 1, shd);
}

// f2: 4 blocks/batch, vec1 (256 px/block), 128 strong planes
__device__ void passb_f2(const float* __restrict__ f2, int b, int pb,
                         float* ns, int* sidx, double* shd) {
  int t = threadIdx.x;
  {
    float s = 0.f;
    const float* pp = g_np2 + b * 8 * 256 + t;
#pragma unroll 8
    for (int k = 0; k < 8; k++) s += pp[k * 256];
    ns[t] = s;
  }
  __syncthreads();
  rank_strong<256>(ns, sidx);
  int p0 = pb * 256 + t;
  const float* xb = f2 + (size_t)b * 256 * 1024 + p0;
  float s0 = 0.f;
#pragma unroll 8
  for (int k = 0; k < 128; k++) {
    s0 += xb[(size_t)sidx[k] * 1024];
  }
  float pa = g_ps2[(size_t)b * 1024 + p0];
  const float inv = 1.f / 128.f;
  float d0 = sigmoidf_((pa - s0) * inv) - sigmoidf_(s0 * inv);
  block_add_double(d0 * d0, 2, shd);
}

__global__ void __launch_bounds__(256) k_passB(
    const float* __restrict__ f0, const float* __restrict__ f1,
    const float* __restrict__ f2) {
  __shared__ float ns[256];
  __shared__ int sidx[128];
  __shared__ double shd[8];
  int bid = blockIdx.x;
  // f2 first (still warm in L2 from passA), then f1, then f0
  if (bid < 128) { passb_f2(f2, bid >> 2, bid & 3, ns, sidx, shd); return; }
  bid -= 128;
  if (bid < 256) { passb_f1(f1, bid >> 3, bid & 7, ns, sidx, shd); return; }
  bid -= 256;
  passb_f0(f0, bid >> 4, bid & 15, ns, sidx, shd);
}

// =========================== FINAL ===========================
__global__ void k_final(float* __restrict__ out) {
  if (threadIdx.x == 0) {
    double lm = 0.0;
    for (int i = 0; i < 32; i++) lm += g_main_part[i];
    double l_main = lm / 32.0;
    double ifd0 = g_acc[0] / (32.0 * 128.0 * 128.0);
    double ifd1 = g_acc[1] / (32.0 * 64.0 * 64.0);
    double ifd2 = g_acc[2] / (32.0 * 32.0 * 32.0);
    double l_ifd = (ifd0 + ifd1 + ifd2) / 3.0;
    double scr0 = g_acc[3] / (32.0 * 64.0 * 128.0 * 128.0);
    double scr1 = g_acc[4] / (32.0 * 128.0 * 64.0 * 64.0);
    double l_scr = (scr0 + scr1) / 2.0;
    double total = l_main + 0.015 * l_scr + 0.015 * l_ifd;
    out[0] = (float)total;
    out[1] = (float)l_main;
    out[2] = (float)l_scr;
    out[3] = (float)l_ifd;
    for (int i = 0; i < 8; i++) g_acc[i] = 0.0;   // reset for next replay
  }
}

// =========================== HOST: constant channel permutations ===========================
static void tf_h(unsigned k0, unsigned k1, unsigned x0, unsigned x1,
                 unsigned* o0, unsigned* o1) {
  unsigned ks2 = 0x1BD11BDAu ^ k0 ^ k1;
#define TFRH(r) { x0 += x1; x1 = (x1 << (r)) | (x1 >> (32 - (r))); x1 ^= x0; }
  x0 += k0; x1 += k1;
  TFRH(13) TFRH(15) TFRH(26) TFRH(6)   x0 += k1;  x1 += ks2 + 1u;
  TFRH(17) TFRH(29) TFRH(16) TFRH(24)  x0 += ks2; x1 += k0 + 2u;
  TFRH(13) TFRH(15) TFRH(26) TFRH(6)   x0 += k0;  x1 += k1 + 3u;
  TFRH(17) TFRH(29) TFRH(16) TFRH(24)  x0 += k1;  x1 += ks2 + 4u;
  TFRH(13) TFRH(15) TFRH(26) TFRH(6)   x0 += ks2; x1 += k0 + 5u;
#undef TFRH
  *o0 = x0; *o1 = x1;
}

static void compute_sel(Sel* S) {
  for (int i = 0; i < 2; i++) {
    unsigned kf0, kf1, a0, a1, b0, b1, c0, c1, d0, d1;
    tf_h(0u, 42u, 0u, (unsigned)i, &kf0, &kf1);
    tf_h(kf0, kf1, 0u, 2u, &a0, &a1);
    tf_h(kf0, kf1, 1u, 3u, &b0, &b1);
    unsigned kt0 = a1, kt1 = b1;
    tf_h(kt0, kt1, 0u, 2u, &c0, &c1);
    tf_h(kt0, kt1, 1u, 3u, &d0, &d1);
    unsigned sk0 = c1, sk1 = d1;
    (void)a0; (void)b0; (void)c0; (void)d0;
    unsigned keys[256];
    for (int j = 0; j < 128; j++) {
      unsigned y0, y1;
      tf_h(sk0, sk1, (unsigned)j, (unsigned)(j + 128), &y0, &y1);
      keys[j] = y0; keys[j + 128] = y1;
    }
    int perm[256];
    for (int t = 0; t < 256; t++) {
      unsigned my = keys[t];
      int rank = 0;
      for (int j = 0; j < 256; j++) {
        unsigned kj = keys[j];
        rank += (kj < my) || (kj == my && j < t);
      }
      perm[rank] = t;
    }
    if (i == 0) { for (int t = 0; t < 64;  t++) S->s0[t] = perm[t]; }
    else        { for (int t = 0; t < 128; t++) S->s1[t] = perm[t]; }
  }
}

extern "C" void kernel_launch(void* const* d_in, const int* in_sizes, int n_in,
                              void* d_out, int out_size) {
  const float* pred = (const float*)d_in[0];
  const float* f0   = (const float*)d_in[1];   // (32, 64, 128, 128)
  const float* f1   = (const float*)d_in[2];   // (32, 128, 64, 64)
  const float* f2   = (const float*)d_in[3];   // (32, 256, 32, 32)
  const int*   tgt  = (const int*)d_in[4];     // int32 (JAX x64 disabled)
  float* out = (float*)d_out;

  Sel sel;
  compute_sel(&sel);                            // deterministic constants

  k_passA<<<1824, 256>>>(pred, f0, f1, f2, tgt, sel);  // 1024 f0 + 512 f1 + 256 f2 + 32 main
  k_passB<<<896, 256>>>(f0, f1, f2);                   // 128 f2 + 256 f1 + 512 f0
  k_final<<<1, 32>>>(out);
}